// round 6
// baseline (speedup 1.0000x reference)
#include <cuda_runtime.h>
#include <cstdint>

#define N_ITEMS 500000
#define DIM 64
#define BATCH 1024
#define TILE 64            // items per smem tile (16 KB)
#define ITEMS_PER_CTA 2048 // -> 245 item chunks
#define QB 256             // queries per CTA (8 warps x 32 lanes)

// Cross-CTA reduction scratch: packed (ordered_float(score) << 32) | ~index
__device__ unsigned long long g_best[BATCH];

__device__ __forceinline__ unsigned int f2ord(float f) {
    unsigned int b = __float_as_uint(f);
    return (b & 0x80000000u) ? ~b : (b | 0x80000000u);
}
__device__ __forceinline__ float ord2f(unsigned int o) {
    unsigned int b = (o & 0x80000000u) ? (o & 0x7FFFFFFFu) : ~o;
    return __uint_as_float(b);
}

__global__ void reset_kernel() {
    int i = blockIdx.x * blockDim.x + threadIdx.x;
    if (i < BATCH) {
        float ninf = __uint_as_float(0xFF800000u); // -inf
        g_best[i] = ((unsigned long long)f2ord(ninf) << 32) | 0xFFFFFFFFull;
    }
}

__global__ __launch_bounds__(256, 2)
void sim_kernel(const float* __restrict__ emb,
                const int* __restrict__ item_idx) {
    __shared__ float4 tile[TILE * (DIM / 4)]; // 16 KB

    const int lane = threadIdx.x & 31;
    const int warp = threadIdx.x >> 5;
    const int q = blockIdx.y * QB + warp * 32 + lane;

    // item_idx is int32 (JAX default config demotes int64 -> int32).
    int self = item_idx[q] - 1;
    if (self < 0) self += N_ITEMS;              // python negative-index wrap
    self = max(0, min(self, N_ITEMS - 1));      // defensive clamp

    // Query vector resident in registers (64 floats = 16 float4)
    float4 qv[16];
    {
        const float4* qrow = (const float4*)(emb + (size_t)self * DIM);
        #pragma unroll
        for (int i = 0; i < 16; i++) qv[i] = __ldg(&qrow[i]);
    }

    float best = __uint_as_float(0xFF800000u);  // -inf
    int   bidx = 0;

    const int chunk_base = blockIdx.x * ITEMS_PER_CTA;
    const int chunk_end  = min(chunk_base + ITEMS_PER_CTA, N_ITEMS);

    for (int tb = chunk_base; tb < chunk_end; tb += TILE) {
        const int nItems = min(TILE, chunk_end - tb);
        const int nf4 = nItems * (DIM / 4);
        const float4* src = (const float4*)(emb + (size_t)tb * DIM);

        __syncthreads(); // previous tile fully consumed
        for (int i = threadIdx.x; i < nf4; i += 256) tile[i] = src[i];
        __syncthreads();

        for (int t = 0; t < nItems; t++) {
            const float4* e = &tile[t * 16];
            float acc0 = 0.f, acc1 = 0.f;
            #pragma unroll
            for (int k = 0; k < 16; k += 2) {
                float4 v0 = e[k];
                float4 v1 = e[k + 1];
                acc0 = fmaf(qv[k].x,     v0.x, acc0);
                acc0 = fmaf(qv[k].y,     v0.y, acc0);
                acc0 = fmaf(qv[k].z,     v0.z, acc0);
                acc0 = fmaf(qv[k].w,     v0.w, acc0);
                acc1 = fmaf(qv[k + 1].x, v1.x, acc1);
                acc1 = fmaf(qv[k + 1].y, v1.y, acc1);
                acc1 = fmaf(qv[k + 1].z, v1.z, acc1);
                acc1 = fmaf(qv[k + 1].w, v1.w, acc1);
            }
            float acc = acc0 + acc1;
            int j = tb + t;
            // strict > keeps first (lowest-index) occurrence, matching argmax
            if (acc > best && j != self) { best = acc; bidx = j; }
        }
    }

    unsigned long long packed =
        ((unsigned long long)f2ord(best) << 32) | (unsigned int)(~bidx);
    atomicMax(&g_best[q], packed);
}

__global__ void finalize_kernel(const float* __restrict__ minv,
                                const float* __restrict__ maxv,
                                float* __restrict__ out) {
    int i = blockIdx.x * blockDim.x + threadIdx.x;
    if (i < BATCH) {
        unsigned long long p = g_best[i];
        float raw = ord2f((unsigned int)(p >> 32));
        int   idx = (int)(~(unsigned int)(p & 0xFFFFFFFFull));
        float mn = minv[0], mx = maxv[0];
        float score = (raw - mn) / (mx - mn);
        // JAX promotion: (int32 indices, float32 scores) -> float32 output.
        out[i]         = (float)(idx + 1);    // indices (argmax + 1), exact <2^24
        out[BATCH + i] = score;               // normalized scores
    }
}

extern "C" void kernel_launch(void* const* d_in, const int* in_sizes, int n_in,
                              void* d_out, int out_size) {
    const float* emb = (const float*)d_in[0];
    const int*   idx = (const int*)d_in[1];
    const float* mn  = (const float*)d_in[2];
    const float* mx  = (const float*)d_in[3];

    reset_kernel<<<(BATCH + 255) / 256, 256>>>();

    dim3 grid((N_ITEMS + ITEMS_PER_CTA - 1) / ITEMS_PER_CTA, BATCH / QB);
    sim_kernel<<<grid, 256>>>(emb, idx);

    finalize_kernel<<<(BATCH + 255) / 256, 256>>>(mn, mx, (float*)d_out);
}